// round 9
// baseline (speedup 1.0000x reference)
#include <cuda_runtime.h>
#include <cuda_bf16.h>
#include <cstdint>

// MXFP8 e4m3 block-32 quantize->dequantize.
// One thread handles TWO float4 tiles (8 elems) from two adjacent 256-thread
// spans (2 independent LDG.128s in flight). 8 consecutive threads form one
// 32-element block. Block amax is computed as an UNSIGNED-INT max on the
// abs bit patterns (valid for non-NaN floats) and reduced across the 8-lane
// group with a single REDUX.SYNC.MAX.U32 instead of a 3-deep shuffle chain,
// cutting ~50 cycles off the load->store dependency path per tile.
// All scale math is exact powers of two via exponent-bit manipulation
// (bit-exact vs the reference).

__device__ __forceinline__ float blk_scale_u(unsigned mbits, float& inv_scale) {
    // shared_exp = floor(log2(amax)) - 8, clamped at -127.
    int ef = (int)(mbits >> 23);               // biased exponent of block amax
    int se = (ef == 0) ? -127 : (ef - 127 - 8);
    se = max(se, -127);
    inv_scale = __uint_as_float((unsigned)(127 - se) << 23);
    return (se >= -126) ? __uint_as_float((unsigned)(se + 127) << 23)
                        : __uint_as_float(0x00400000u);   // 2^-127 denormal
}

__device__ __forceinline__ float q1(float a, float inv_scale, float scale) {
    float as = fabsf(a) * inv_scale;           // exact: power-of-two multiply
    unsigned b = __float_as_uint(as);
    int pe = (int)(b >> 23) - 127;             // denormal 'as' -> very negative
    pe = max(pe, -6);                          // MIN_EXP clamp (covers denorms)
    float lsh = __uint_as_float((unsigned)(3 - pe + 127) << 23);   // 2^(3-pe)
    float ils = __uint_as_float((unsigned)(pe - 3 + 127) << 23);   // 2^(pe-3)
    float q = floorf(as * lsh + 0.5f);         // round half away from zero
    float d = fminf(q * ils, 448.0f);          // saturate e4m3 max norm
    return copysignf(d * scale, a);
}

__device__ __forceinline__ unsigned amax4_bits(float4 v) {
    unsigned a = __float_as_uint(v.x) & 0x7fffffffu;
    unsigned b = __float_as_uint(v.y) & 0x7fffffffu;
    unsigned c = __float_as_uint(v.z) & 0x7fffffffu;
    unsigned d = __float_as_uint(v.w) & 0x7fffffffu;
    return max(max(a, b), max(c, d));
}

__global__ __launch_bounds__(256) void mxq_kernel(const float4* __restrict__ x,
                                                  float4* __restrict__ out,
                                                  int n4) {
    int i0 = blockIdx.x * 512 + threadIdx.x;   // tile A
    int i1 = i0 + 256;                         // tile B (independent load)
    bool p0 = i0 < n4, p1 = i1 < n4;

    float4 v0, v1;
    if (p0) v0 = __ldcs(x + i0);               // streaming: evict-first
    if (p1) v1 = __ldcs(x + i1);

    // 8-lane member mask for this thread's block group (lanes [g*8, g*8+8))
    unsigned lane = threadIdx.x & 31u;
    unsigned gmask = 0xFFu << (lane & 24u);

    // single-instruction block reduction on abs bit patterns
    unsigned m0 = __reduce_max_sync(gmask, amax4_bits(v0));
    unsigned m1 = __reduce_max_sync(gmask, amax4_bits(v1));

    float is0, is1;
    float s0 = blk_scale_u(m0, is0);
    float s1 = blk_scale_u(m1, is1);

    if (p0) {
        float4 r;
        r.x = q1(v0.x, is0, s0); r.y = q1(v0.y, is0, s0);
        r.z = q1(v0.z, is0, s0); r.w = q1(v0.w, is0, s0);
        __stcs(out + i0, r);
    }
    if (p1) {
        float4 r;
        r.x = q1(v1.x, is1, s1); r.y = q1(v1.y, is1, s1);
        r.z = q1(v1.z, is1, s1); r.w = q1(v1.w, is1, s1);
        __stcs(out + i1, r);
    }
}

extern "C" void kernel_launch(void* const* d_in, const int* in_sizes, int n_in,
                              void* d_out, int out_size) {
    const float4* x = (const float4*)d_in[0];
    float4* out = (float4*)d_out;
    int n = in_sizes[0];            // 8192*8192, divisible by 4
    int n4 = n >> 2;
    int blocks = (n4 + 511) / 512;  // 512 float4s (two 256-tiles) per block
    mxq_kernel<<<blocks, 256>>>(x, out, n4);
}

// round 10
// speedup vs baseline: 1.0012x; 1.0012x over previous
#include <cuda_runtime.h>
#include <cuda_bf16.h>
#include <cstdint>

// MXFP8 e4m3 block-32 quantize->dequantize.
// One thread handles FOUR float4 tiles (16 elems) from four adjacent
// 256-thread spans -> 4 independent LDG.128s front-batched per thread.
// 8 consecutive threads form one 32-element block; block amax via 3
// butterfly shuffles (xor 1,2,4), four chains interleaved. All scale math
// is exact powers of two via exponent-bit manipulation (bit-exact vs ref).

__device__ __forceinline__ float blk_scale(float m, float& inv_scale) {
    // shared_exp = floor(log2(amax)) - 8, clamped at -127.
    unsigned mb = __float_as_uint(m);
    int ef = (int)(mb >> 23);
    int se = (ef == 0) ? -127 : (ef - 127 - 8);
    se = max(se, -127);
    inv_scale = __uint_as_float((unsigned)(127 - se) << 23);
    return (se >= -126) ? __uint_as_float((unsigned)(se + 127) << 23)
                        : __uint_as_float(0x00400000u);   // 2^-127 denormal
}

__device__ __forceinline__ float q1(float a, float inv_scale, float scale) {
    float as = fabsf(a) * inv_scale;           // exact: power-of-two multiply
    unsigned b = __float_as_uint(as);
    int pe = (int)(b >> 23) - 127;             // denormal 'as' -> very negative
    pe = max(pe, -6);                          // MIN_EXP clamp (covers denorms)
    float lsh = __uint_as_float((unsigned)(3 - pe + 127) << 23);   // 2^(3-pe)
    float ils = __uint_as_float((unsigned)(pe - 3 + 127) << 23);   // 2^(pe-3)
    float q = floorf(as * lsh + 0.5f);         // round half away from zero
    float d = fminf(q * ils, 448.0f);          // saturate e4m3 max norm
    return copysignf(d * scale, a);
}

__device__ __forceinline__ float amax4(float4 v) {
    return fmaxf(fmaxf(fabsf(v.x), fabsf(v.y)), fmaxf(fabsf(v.z), fabsf(v.w)));
}

__device__ __forceinline__ float4 qtile(float4 v, float is, float s) {
    float4 r;
    r.x = q1(v.x, is, s); r.y = q1(v.y, is, s);
    r.z = q1(v.z, is, s); r.w = q1(v.w, is, s);
    return r;
}

__global__ __launch_bounds__(256) void mxq_kernel(const float4* __restrict__ x,
                                                  float4* __restrict__ out,
                                                  int n4) {
    int base = blockIdx.x * 1024 + threadIdx.x;

    if (base + 768 < n4) {
        // fast path: all four tiles in range -> unconditional batched loads
        float4 v0 = __ldcs(x + base);
        float4 v1 = __ldcs(x + base + 256);
        float4 v2 = __ldcs(x + base + 512);
        float4 v3 = __ldcs(x + base + 768);

        float m0 = amax4(v0), m1 = amax4(v1), m2 = amax4(v2), m3 = amax4(v3);
        m0 = fmaxf(m0, __shfl_xor_sync(0xffffffffu, m0, 1));
        m1 = fmaxf(m1, __shfl_xor_sync(0xffffffffu, m1, 1));
        m2 = fmaxf(m2, __shfl_xor_sync(0xffffffffu, m2, 1));
        m3 = fmaxf(m3, __shfl_xor_sync(0xffffffffu, m3, 1));
        m0 = fmaxf(m0, __shfl_xor_sync(0xffffffffu, m0, 2));
        m1 = fmaxf(m1, __shfl_xor_sync(0xffffffffu, m1, 2));
        m2 = fmaxf(m2, __shfl_xor_sync(0xffffffffu, m2, 2));
        m3 = fmaxf(m3, __shfl_xor_sync(0xffffffffu, m3, 2));
        m0 = fmaxf(m0, __shfl_xor_sync(0xffffffffu, m0, 4));
        m1 = fmaxf(m1, __shfl_xor_sync(0xffffffffu, m1, 4));
        m2 = fmaxf(m2, __shfl_xor_sync(0xffffffffu, m2, 4));
        m3 = fmaxf(m3, __shfl_xor_sync(0xffffffffu, m3, 4));

        float is0, is1, is2, is3;
        float s0 = blk_scale(m0, is0);
        float s1 = blk_scale(m1, is1);
        float s2 = blk_scale(m2, is2);
        float s3 = blk_scale(m3, is3);

        __stcs(out + base,       qtile(v0, is0, s0));
        __stcs(out + base + 256, qtile(v1, is1, s1));
        __stcs(out + base + 512, qtile(v2, is2, s2));
        __stcs(out + base + 768, qtile(v3, is3, s3));
    } else {
        // tail path (unused for 8192x8192, kept for generality)
        #pragma unroll
        for (int t = 0; t < 4; t++) {
            int i = base + t * 256;
            float4 v = (i < n4) ? __ldcs(x + i) : make_float4(0.f, 0.f, 0.f, 0.f);
            float m = amax4(v);
            m = fmaxf(m, __shfl_xor_sync(0xffffffffu, m, 1));
            m = fmaxf(m, __shfl_xor_sync(0xffffffffu, m, 2));
            m = fmaxf(m, __shfl_xor_sync(0xffffffffu, m, 4));
            float is;
            float s = blk_scale(m, is);
            if (i < n4) __stcs(out + i, qtile(v, is, s));
        }
    }
}

extern "C" void kernel_launch(void* const* d_in, const int* in_sizes, int n_in,
                              void* d_out, int out_size) {
    const float4* x = (const float4*)d_in[0];
    float4* out = (float4*)d_out;
    int n = in_sizes[0];             // 8192*8192, divisible by 4
    int n4 = n >> 2;
    int blocks = (n4 + 1023) / 1024; // 1024 float4s (four 256-tiles) per block
    mxq_kernel<<<blocks, 256>>>(x, out, n4);
}